// round 17
// baseline (speedup 1.0000x reference)
#include <cuda_runtime.h>
#include <cuda_bf16.h>
#include <math.h>
#include <stdint.h>

// Shapes: B=1, S=128, L=256, D=768 (H=12, dh=64), M = S*L = 32768, 3D = 2304.
#define SQ   128
#define LQ   256
#define DQ   768
#define HQ   12
#define DHQ  64
#define MQ   (SQ * LQ)      // 32768
#define N3Q  (3 * DQ)       // 2304
#define NSP  8

#define QK_U32   12582912
#define QK_ELE   25165824
#define AT_ELE   786432

// ---------------- scratch ----------------
__device__ float    g_qkv[(size_t)MQ * N3Q];        // 302 MB
__device__ float    g_attn[HQ * LQ * LQ];           // 3 MB
__device__ float    g_tmp[(size_t)MQ * DQ];         // 100 MB: A int8 quant / row_av out
__device__ float    g_out1[(size_t)MQ * DQ];        // 100 MB: logit partials, then LN1 out
__device__ float    g_wsplit[2 * (size_t)N3Q * DQ]; // 14 MB : W int8 quant, then attn splits
__device__ uint32_t g_qksp[4 * (size_t)QK_U32];     // 201 MB: Q/K splits, then V'' splits

// ================= helpers ==================
__device__ __forceinline__ void mma_bf16_16x8x16(float* c, const uint32_t* a, const uint32_t* b) {
    asm volatile(
        "mma.sync.aligned.m16n8k16.row.col.f32.bf16.bf16.f32 "
        "{%0,%1,%2,%3}, {%4,%5,%6,%7}, {%8,%9}, {%0,%1,%2,%3};"
        : "+f"(c[0]), "+f"(c[1]), "+f"(c[2]), "+f"(c[3])
        : "r"(a[0]), "r"(a[1]), "r"(a[2]), "r"(a[3]), "r"(b[0]), "r"(b[1]));
}

__device__ __forceinline__ void imma_s8(int* c, const uint32_t* a, const uint32_t* b) {
    asm volatile(
        "mma.sync.aligned.m16n8k32.row.col.s32.s8.s8.s32 "
        "{%0,%1,%2,%3}, {%4,%5,%6,%7}, {%8,%9}, {%0,%1,%2,%3};"
        : "+r"(c[0]), "+r"(c[1]), "+r"(c[2]), "+r"(c[3])
        : "r"(a[0]), "r"(a[1]), "r"(a[2]), "r"(a[3]), "r"(b[0]), "r"(b[1]));
}

__device__ __forceinline__ uint32_t smem_u32(const void* p) {
    uint32_t a;
    asm("{ .reg .u64 t; cvta.to.shared.u64 t, %1; cvt.u32.u64 %0, t; }"
        : "=r"(a) : "l"(p));
    return a;
}

__device__ __forceinline__ void cpasync16(uint32_t dst, const void* src) {
    asm volatile("cp.async.cg.shared.global [%0], [%1], 16;" :: "r"(dst), "l"(src));
}
__device__ __forceinline__ void cp_commit() {
    asm volatile("cp.async.commit_group;" ::: "memory");
}
__device__ __forceinline__ void cp_wait1() {
    asm volatile("cp.async.wait_group 1;" ::: "memory");
}

__device__ __forceinline__ void pack_hi_lo(float x, float y, uint32_t& hi, uint32_t& lo) {
    __nv_bfloat16 hx = __float2bfloat16_rn(x);
    __nv_bfloat16 hy = __float2bfloat16_rn(y);
    __nv_bfloat16 lx = __float2bfloat16_rn(x - __bfloat162float(hx));
    __nv_bfloat16 ly = __float2bfloat16_rn(y - __bfloat162float(hy));
    hi = ((uint32_t)__bfloat16_as_ushort(hy) << 16) | __bfloat16_as_ushort(hx);
    lo = ((uint32_t)__bfloat16_as_ushort(ly) << 16) | __bfloat16_as_ushort(lx);
}

// =================================================================
// Kernel Q0: per-row int8 16-bit fixed-point quantization.
// x ~= scale[row] * (128*qh + ql).  One block (192 thr) per row.
// =================================================================
__global__ __launch_bounds__(192) void quant_rows(
    const float* __restrict__ in, uint32_t* __restrict__ qhi,
    uint32_t* __restrict__ qlo, float* __restrict__ scale)
{
    const int row = blockIdx.x;
    const int t = threadIdx.x;
    float4 v = ((const float4*)(in + (size_t)row * DQ))[t];
    float m = fmaxf(fmaxf(fabsf(v.x), fabsf(v.y)), fmaxf(fabsf(v.z), fabsf(v.w)));

    __shared__ float red[6];
#pragma unroll
    for (int o = 16; o > 0; o >>= 1) m = fmaxf(m, __shfl_xor_sync(0xffffffffu, m, o));
    if ((t & 31) == 0) red[t >> 5] = m;
    __syncthreads();
    float mm = red[0];
#pragma unroll
    for (int k = 1; k < 6; k++) mm = fmaxf(mm, red[k]);
    mm = fmaxf(mm, 1e-20f);

    const float inv = 16256.f / mm;
    int ih[4], il[4];
#pragma unroll
    for (int u = 0; u < 4; u++) {
        float q  = (&v.x)[u] * inv;
        float qh = rintf(q * 0.0078125f);     // q/128
        float ql = rintf(q - qh * 128.f);
        ih[u] = (int)qh;
        il[u] = (int)ql;
    }
    uint32_t ph = (uint32_t)(ih[0] & 255) | ((uint32_t)(ih[1] & 255) << 8)
                | ((uint32_t)(ih[2] & 255) << 16) | ((uint32_t)(ih[3] & 255) << 24);
    uint32_t pl = (uint32_t)(il[0] & 255) | ((uint32_t)(il[1] & 255) << 8)
                | ((uint32_t)(il[2] & 255) << 16) | ((uint32_t)(il[3] & 255) << 24);
    qhi[(size_t)row * 192 + t] = ph;
    qlo[(size_t)row * 192 + t] = pl;
    if (t == 0) scale[row] = mm * (1.f / 16256.f);
}

// =================================================================
// Kernel 1: int8 x3-term GEMM: C[M,2304] = A*B^T + bias.
// CTA tile 128x64, K-chunk 32, cp.async 2-stage, 8 warps (4m x 2n),
// warp tile 32x32. smem rows pitch 12 u32 (conflict-free mod 32).
// C = sa[m]*sb[n]*(16384*P1 + 128*P2) + bias, P int32 exact.
// =================================================================
#define I8_PITCH   12
#define I8_STAGE   4608              // u32 per stage (384 rows * 12)
#define I8_STAGE_B 18432             // bytes

__global__ __launch_bounds__(256, 2) void qkv_gemm_i8(
    const uint8_t* __restrict__ Ah8, const uint8_t* __restrict__ Al8,
    const uint8_t* __restrict__ Bh8, const uint8_t* __restrict__ Bl8,
    const float* __restrict__ sA, const float* __restrict__ sB,
    const float* __restrict__ bias, float* __restrict__ C)
{
    __shared__ uint32_t smi[2 * I8_STAGE];
    const int tid = threadIdx.x;
    const int m0 = blockIdx.y * 128;
    const int n0 = blockIdx.x * 64;
    const int w  = tid >> 5;
    const int l  = tid & 31;
    const int g  = l >> 2;
    const int q  = l & 3;
    const int wm = (w & 3) * 32;
    const int wn = (w >> 2) * 32;
    const uint32_t smb = smem_u32(smi);

    // staging: 768 x 16B units; thread handles units tid, tid+256, tid+512.
    const uint8_t* src[3];
    uint32_t dst[3];
#pragma unroll
    for (int k = 0; k < 3; k++) {
        const int u = tid + k * 256;
        const int row = u >> 1, half = u & 1;
        const uint8_t* p;
        if (row < 128)      p = Ah8 + (size_t)(m0 + row) * DQ;
        else if (row < 256) p = Al8 + (size_t)(m0 + row - 128) * DQ;
        else if (row < 320) p = Bh8 + (size_t)(n0 + row - 256) * DQ;
        else                p = Bl8 + (size_t)(n0 + row - 320) * DQ;
        src[k] = p + half * 16;
        dst[k] = (uint32_t)(row * I8_PITCH + half * 4) * 4;
    }

#define I8_ISSUE(ch2) do {                                                    \
    const uint32_t b = smb + ((ch2) & 1) * I8_STAGE_B;                        \
    cpasync16(b + dst[0], src[0] + (ch2) * 32);                               \
    cpasync16(b + dst[1], src[1] + (ch2) * 32);                               \
    cpasync16(b + dst[2], src[2] + (ch2) * 32);                               \
} while (0)

    int P1[2][4][4], P2[2][4][4];
#pragma unroll
    for (int mi = 0; mi < 2; mi++)
#pragma unroll
        for (int ni = 0; ni < 4; ni++)
#pragma unroll
            for (int t2 = 0; t2 < 4; t2++) { P1[mi][ni][t2] = 0; P2[mi][ni][t2] = 0; }

    I8_ISSUE(0); cp_commit();
    I8_ISSUE(1); cp_commit();

    const int NCH = DQ / 32;   // 24
    for (int ch = 0; ch < NCH; ch++) {
        cp_wait1();
        __syncthreads();

        const uint32_t* S   = smi + (ch & 1) * I8_STAGE;
        const uint32_t* SAh = S;
        const uint32_t* SAl = S + 128 * I8_PITCH;
        const uint32_t* SBh = S + 256 * I8_PITCH;
        const uint32_t* SBl = S + 320 * I8_PITCH;

        uint32_t ah[2][4], al[2][4], bh[4][2], bl[4][2];
#pragma unroll
        for (int mi = 0; mi < 2; mi++) {
            const int r = wm + mi * 16 + g;
            ah[mi][0] = SAh[r * I8_PITCH + q];
            ah[mi][1] = SAh[(r + 8) * I8_PITCH + q];
            ah[mi][2] = SAh[r * I8_PITCH + q + 4];
            ah[mi][3] = SAh[(r + 8) * I8_PITCH + q + 4];
            al[mi][0] = SAl[r * I8_PITCH + q];
            al[mi][1] = SAl[(r + 8) * I8_PITCH + q];
            al[mi][2] = SAl[r * I8_PITCH + q + 4];
            al[mi][3] = SAl[(r + 8) * I8_PITCH + q + 4];
        }
#pragma unroll
        for (int ni = 0; ni < 4; ni++) {
            const int rn = wn + ni * 8 + g;
            bh[ni][0] = SBh[rn * I8_PITCH + q];
            bh[ni][1] = SBh[rn * I8_PITCH + q + 4];
            bl[ni][0] = SBl[rn * I8_PITCH + q];
            bl[ni][1] = SBl[rn * I8_PITCH + q + 4];
        }
#pragma unroll
        for (int mi = 0; mi < 2; mi++)
#pragma unroll
            for (int ni = 0; ni < 4; ni++)
                imma_s8(P1[mi][ni], ah[mi], bh[ni]);
#pragma unroll
        for (int mi = 0; mi < 2; mi++)
#pragma unroll
            for (int ni = 0; ni < 4; ni++)
                imma_s8(P2[mi][ni], ah[mi], bl[ni]);
#pragma unroll
        for (int mi = 0; mi < 2; mi++)
#pragma unroll
            for (int ni = 0; ni < 4; ni++)
                imma_s8(P2[mi][ni], al[mi], bh[ni]);

        __syncthreads();
        if (ch + 2 < NCH) I8_ISSUE(ch + 2);
        cp_commit();
    }

    // epilogue: scale + bias
#pragma unroll
    for (int ni = 0; ni < 4; ni++) {
        const int col = n0 + wn + ni * 8 + 2 * q;
        const float sb0 = sB[col], sb1 = sB[col + 1];
        const float bv0 = bias[col], bv1 = bias[col + 1];
#pragma unroll
        for (int mi = 0; mi < 2; mi++) {
            const int row0 = m0 + wm + mi * 16 + g;
            const float sa0 = sA[row0], sa1 = sA[row0 + 8];
            float f00 = sa0 * sb0 * (16384.f * __int2float_rn(P1[mi][ni][0])
                                    + 128.f * __int2float_rn(P2[mi][ni][0])) + bv0;
            float f01 = sa0 * sb1 * (16384.f * __int2float_rn(P1[mi][ni][1])
                                    + 128.f * __int2float_rn(P2[mi][ni][1])) + bv1;
            float f10 = sa1 * sb0 * (16384.f * __int2float_rn(P1[mi][ni][2])
                                    + 128.f * __int2float_rn(P2[mi][ni][2])) + bv0;
            float f11 = sa1 * sb1 * (16384.f * __int2float_rn(P1[mi][ni][3])
                                    + 128.f * __int2float_rn(P2[mi][ni][3])) + bv1;
            *(float2*)(C + (size_t)row0 * N3Q + col)       = make_float2(f00, f01);
            *(float2*)(C + (size_t)(row0 + 8) * N3Q + col) = make_float2(f10, f11);
        }
    }
#undef I8_ISSUE
}

// =================================================================
// Kernel 0: elementwise bf16 hi/lo split (attn splits)
// =================================================================
__global__ __launch_bounds__(256) void split_bf16(
    const float* __restrict__ in, __nv_bfloat16* __restrict__ hi,
    __nv_bfloat16* __restrict__ lo, int n4)
{
    int i = blockIdx.x * 256 + threadIdx.x;
    if (i >= n4) return;
    float4 v = ((const float4*)in)[i];
    uint32_t h0, l0, h1, l1;
    pack_hi_lo(v.x, v.y, h0, l0);
    pack_hi_lo(v.z, v.w, h1, l1);
    ((uint2*)hi)[i] = make_uint2(h0, h1);
    ((uint2*)lo)[i] = make_uint2(l0, l1);
}

// =================================================================
// Kernel 0b: split + transpose Q,K into per-head K-major bf16 hi/lo.
// =================================================================
__global__ __launch_bounds__(256) void split_qk(
    const float* __restrict__ qkv, uint32_t* __restrict__ qksp)
{
    const int idx = blockIdx.x * 256 + threadIdx.x;
    const int arr = idx / QK_U32;
    const int r   = idx - arr * QK_U32;
    const int h   = r >> 20;
    const int rem = r & 0xFFFFF;
    const int i   = rem >> 12;
    const int kk2 = rem & 4095;
    const int s   = kk2 >> 5;
    const int c   = (kk2 & 31) << 1;

    const float2 v = *(const float2*)(qkv + (size_t)(s * LQ + i) * N3Q
                                      + arr * DQ + h * DHQ + c);
    uint32_t hi, lo;
    pack_hi_lo(v.x, v.y, hi, lo);
    const uint32_t base = (uint32_t)arr * (2u * QK_U32);
    qksp[base + r]           = hi;
    qksp[base + QK_U32 + r]  = lo;
}

// =================================================================
// Kernel 0c: split + transpose V into V''[h][(s,d)][j] bf16 hi/lo.
// =================================================================
__global__ __launch_bounds__(256) void split_v(
    const float* __restrict__ qkv, uint32_t* __restrict__ vsp)
{
    extern __shared__ float T[];   // [64][258]
    const int s = blockIdx.x;
    const int h = blockIdx.y;
    const int t = threadIdx.x;

#pragma unroll
    for (int k = 0; k < 64; k++) {
        int idx = t + k * 256;
        int j = idx >> 6, d = idx & 63;
        T[d * 258 + j] = qkv[(size_t)(s * LQ + j) * N3Q + 2 * DQ + h * DHQ + d];
    }
    __syncthreads();

#pragma unroll
    for (int k = 0; k < 32; k++) {
        int idx = t + k * 256;
        int d = idx >> 7, j2 = idx & 127;
        uint32_t hi, lo;
        pack_hi_lo(T[d * 258 + 2 * j2], T[d * 258 + 2 * j2 + 1], hi, lo);
        const uint32_t off = (uint32_t)(h * 8192 + s * 64 + d) * 128 + j2;
        vsp[off]          = hi;
        vsp[QK_U32 + off] = lo;
    }
}

// =================================================================
// Generic bf16 mma tile body (R13/R14 winner)
// =================================================================
#define MV2_STAGE_B  40960
#define MV2_ARR_B    10240
#define MV2_SMEM     (2 * MV2_STAGE_B)

#define MMA_TILE_BODY(pAhi_, pAlo_, pBhi_, pBlo_, NCH_)                        \
    float c[2][8][4];                                                          \
    _Pragma("unroll")                                                          \
    for (int mi = 0; mi < 2; mi++)                                             \
        _Pragma("unroll")                                                      \
        for (int ni = 0; ni < 8; ni++)                                         \
            _Pragma("unroll")                                                  \
            for (int t2 = 0; t2 < 4; t2++) c[mi][ni][t2] = 0.f;                \
    { const uint32_t d0 = smb + rowoff;                                        \
      cpasync16(d0, pAhi_); cpasync16(d0 + 16, pAhi_ + 8);                     \
      cpasync16(d0 + MV2_ARR_B, pAlo_); cpasync16(d0 + MV2_ARR_B + 16, pAlo_ + 8); \
      cpasync16(d0 + 2*MV2_ARR_B, pBhi_); cpasync16(d0 + 2*MV2_ARR_B + 16, pBhi_ + 8); \
      cpasync16(d0 + 3*MV2_ARR_B, pBlo_); cpasync16(d0 + 3*MV2_ARR_B + 16, pBlo_ + 8); } \
    cp_commit();                                                               \
    { const uint32_t d1 = smb + MV2_STAGE_B + rowoff;                          \
      cpasync16(d1, pAhi_ + 32); cpasync16(d1 + 16, pAhi_ + 40);               \
      cpasync16(d1 + MV2_ARR_B, pAlo_ + 32); cpasync16(d1 + MV2_ARR_B + 16, pAlo_ + 40); \
      cpasync16(d1 + 2*MV2_ARR_B, pBhi_ + 32); cpasync16(d1 + 2*MV2_ARR_B + 16, pBhi_ + 40); \
      cpasync16(d1 + 3*MV2_ARR_B, pBlo_ + 32); cpasync16(d1 + 3*MV2_ARR_B + 16, pBlo_ + 40); } \
    cp_commit();                                                               \
    for (int ch = 0; ch < (NCH_); ch++) {                                      \
        cp_wait1();                                                            \
        __syncthreads();                                                       \
        const uint32_t* Sw  = sm2 + (ch & 1) * (MV2_STAGE_B / 4);              \
        const uint32_t* A_h = Sw;                                              \
        const uint32_t* A_l = Sw + 2560;                                       \
        const uint32_t* B_h = Sw + 5120;                                       \
        const uint32_t* B_l = Sw + 7680;                                       \
        _Pragma("unroll")                                                      \
        for (int ks = 0; ks < 2; ks++) {                                       \
            const int ws = ks * 8;                                             \
            uint32_t ah[2][4], al[2][4], bh[8][2], bl[8][2];                   \
            _Pragma("unroll")                                                  \
            for (int mi = 0; mi < 2; mi++) {                                   \
                const int r = wm + mi * 16 + g;                                \
                ah[mi][0] = A_h[r * 20 + ws + q];                              \
                ah[mi][1] = A_h[(r + 8) * 20 + ws + q];                        \
                ah[mi][2] = A_h[r * 20 + ws + q + 4];                          \
                ah[mi][3] = A_h[(r + 8) * 20 + ws + q + 4];                    \
                al[mi][0] = A_l[r * 20 + ws + q];                              \
                al[mi][1] = A_l[(r + 8) * 20 + ws + q];                        \
                al[mi][2] = A_l[r * 20 + ws + q + 4];                          \
                al[mi][3] = A_l[(r + 8) * 20 + ws + q + 4];                    \
            }                                                                  \
            _Pragma("unroll")                                                  \
            for (int ni = 0; ni < 8; ni++) {                                   \
                const int rn = wn + ni * 8 + g;                                \
                bh[ni][0] = B_h[rn * 20 + ws + q];                             \
                bh[ni][1] = B_h[rn * 20 + ws + q + 4];                         \
                bl[ni][0] = B_l[rn * 20 + ws + q];                             \
                bl[ni][1] = B_l[rn * 20 + ws + q + 4];                         \
            }                                                                  \
            _Pragma("unroll")                                                  \
            for (int mi = 0; mi < 2; mi++)                                     \
                _Pragma("unroll")                                              \
                for (int ni = 0; ni < 8; ni++)                                 \
                    mma_bf16_16x8x16(c[mi][ni], ah[mi], bh[ni]);               \
            _Pragma("unroll")                                                  \
            for (int mi = 0; mi < 2; mi++)                                     \
                _Pragma("unroll")                                              \
                for (int ni = 0; ni < 8; ni++)                                 \
                    mma_bf16_16x8x16(c[mi][ni], ah[mi], bl[ni]);               \
            _Pragma("unroll")                                                  \
            for (int mi = 0; mi < 2; mi++)                                     \
                _Pragma("unroll")                                              \
                for (int ni = 0; ni < 8; ni++)                                 \
                    mma_bf16_16x8x16(c[mi][ni], al[mi], bh[ni]);               \
        }                                                                      \
        __syncthreads();                                                       \
        if (ch + 2 < (NCH_)) {                                                 \
            const uint32_t dn = smb + ((ch + 2) & 1) * MV2_STAGE_B + rowoff;   \
            const __nv_bfloat16* nA0 = pAhi_ + (ch + 2) * 32;                  \
            const __nv_bfloat16* nA1 = pAlo_ + (ch + 2) * 32;                  \
            const __nv_bfloat16* nB0 = pBhi_ + (ch + 2) * 32;                  \
            const __nv_bfloat16* nB1 = pBlo_ + (ch + 2) * 32;                  \
            cpasync16(dn, nA0); cpasync16(dn + 16, nA0 + 8);                   \
            cpasync16(dn + MV2_ARR_B, nA1); cpasync16(dn + MV2_ARR_B + 16, nA1 + 8); \
            cpasync16(dn + 2*MV2_ARR_B, nB0); cpasync16(dn + 2*MV2_ARR_B + 16, nB0 + 8); \
            cpasync16(dn + 3*MV2_ARR_B, nB1); cpasync16(dn + 3*MV2_ARR_B + 16, nB1 + 8); \
        }                                                                      \
        cp_commit();                                                           \
    }

// =================================================================
// Kernel 2: row logits via bf16 x3-split mma.
// =================================================================
__global__ __launch_bounds__(256, 2) void row_logits_mma(
    const uint32_t* __restrict__ qksp, float* __restrict__ part)
{
    extern __shared__ uint32_t sm2[];
    const int tid = threadIdx.x;
    const int h   = blockIdx.z >> 3;
    const int sp  = blockIdx.z & 7;
    const int i0 = blockIdx.y * 128;
    const int j0 = blockIdx.x * 128;
    const int w  = tid >> 5;
    const int l  = tid & 31;
    const int g  = l >> 2;
    const int q  = l & 3;
    const int wm = (w & 3) * 32;
    const int wn = (w >> 2) * 64;
    const int srow  = tid >> 1;
    const int shalf = tid & 1;
    const uint32_t smb = smem_u32(sm2);
    const uint32_t rowoff = (uint32_t)(srow * 20 + shalf * 8) * 4;

    const __nv_bfloat16* base = (const __nv_bfloat16*)qksp;
    const __nv_bfloat16* pAhi = base + (size_t)(h * 256 + i0 + srow) * 8192 + sp * 1024 + shalf * 16;
    const __nv_bfloat16* pAlo = pAhi + (size_t)QK_ELE;
    const __nv_bfloat16* pBhi = base + 2 * (size_t)QK_ELE
                              + (size_t)(h * 256 + j0 + srow) * 8192 + sp * 1024 + shalf * 16;
    const __nv_bfloat16* pBlo = pBhi + (size_t)QK_ELE;

    MMA_TILE_BODY(pAhi, pAlo, pBhi, pBlo, 32)

    float* dst = part + (size_t)(sp * HQ + h) * (LQ * LQ);
#pragma unroll
    for (int ni = 0; ni < 8; ni++) {
        const int col = j0 + wn + ni * 8 + 2 * q;
#pragma unroll
        for (int mi = 0; mi < 2; mi++) {
            const int row0 = i0 + wm + mi * 16 + g;
            *(float2*)(dst + (size_t)row0 * LQ + col)       = make_float2(c[mi][ni][0], c[mi][ni][1]);
            *(float2*)(dst + (size_t)(row0 + 8) * LQ + col) = make_float2(c[mi][ni][2], c[mi][ni][3]);
        }
    }
}

// =================================================================
// Kernel 2b: row AV via mma.
// =================================================================
__global__ __launch_bounds__(256, 2) void row_av_mma(
    const uint32_t* __restrict__ atsp, const uint32_t* __restrict__ vsp,
    float* __restrict__ outp)
{
    extern __shared__ uint32_t sm2[];
    const int tid = threadIdx.x;
    const int h  = blockIdx.z;
    const int i0 = blockIdx.y * 128;
    const int n0 = blockIdx.x * 128;
    const int w  = tid >> 5;
    const int l  = tid & 31;
    const int g  = l >> 2;
    const int q  = l & 3;
    const int wm = (w & 3) * 32;
    const int wn = (w >> 2) * 64;
    const int srow  = tid >> 1;
    const int shalf = tid & 1;
    const uint32_t smb = smem_u32(sm2);
    const uint32_t rowoff = (uint32_t)(srow * 20 + shalf * 8) * 4;

    const __nv_bfloat16* abase = (const __nv_bfloat16*)atsp;
    const __nv_bfloat16* vbase = (const __nv_bfloat16*)vsp;
    const __nv_bfloat16* pAhi = abase + (size_t)(h * 256 + i0 + srow) * 256 + shalf * 16;
    const __nv_bfloat16* pAlo = pAhi + (size_t)AT_ELE;
    const __nv_bfloat16* pBhi = vbase + (size_t)(h * 8192 + n0 + srow) * 256 + shalf * 16;
    const __nv_bfloat16* pBlo = pBhi + (size_t)QK_ELE;

    MMA_TILE_BODY(pAhi, pAlo, pBhi, pBlo, 8)

    float* dst = outp + (size_t)(h * 256) * 8192;
#pragma unroll
    for (int ni = 0; ni < 8; ni++) {
        const int col = n0 + wn + ni * 8 + 2 * q;
#pragma unroll
        for (int mi = 0; mi < 2; mi++) {
            const int row0 = i0 + wm + mi * 16 + g;
            *(float2*)(dst + (size_t)row0 * 8192 + col)       = make_float2(c[mi][ni][0], c[mi][ni][1]);
            *(float2*)(dst + (size_t)(row0 + 8) * 8192 + col) = make_float2(c[mi][ni][2], c[mi][ni][3]);
        }
    }
}

// =================================================================
// Kernel 3: reduce partials + softmax over last dim (256)
// =================================================================
__global__ __launch_bounds__(256) void softmax_row(
    const float* __restrict__ part, float* __restrict__ attn)
{
    const int row = blockIdx.x;
    const int h = row >> 8;
    const int i = row & 255;
    const int t = threadIdx.x;

    float v = 0.f;
#pragma unroll
    for (int sp = 0; sp < NSP; sp++)
        v += part[((size_t)(sp * HQ + h)) * LQ * LQ + (size_t)i * LQ + t];

    __shared__ float red[8];
    float m = v;
#pragma unroll
    for (int o = 16; o > 0; o >>= 1) m = fmaxf(m, __shfl_xor_sync(0xffffffffu, m, o));
    if ((t & 31) == 0) red[t >> 5] = m;
    __syncthreads();
    float mm = red[0];
#pragma unroll
    for (int k = 1; k < 8; k++) mm = fmaxf(mm, red[k]);
    __syncthreads();

    float e = expf(v - mm);
    float s = e;
#pragma unroll
    for (int o = 16; o > 0; o >>= 1) s += __shfl_xor_sync(0xffffffffu, s, o);
    if ((t & 31) == 0) red[t >> 5] = s;
    __syncthreads();
    float tot = 0.f;
#pragma unroll
    for (int k = 0; k < 8; k++) tot += red[k];

    attn[(size_t)row * LQ + t] = e / tot;
}

// =================================================================
// Kernel 5: add + LN (contiguous residual)
// =================================================================
__global__ __launch_bounds__(256) void add_ln(
    const float* __restrict__ X, const float* __restrict__ R,
    const float* __restrict__ g, const float* __restrict__ b,
    float* __restrict__ out)
{
    const int row = blockIdx.x;
    const int t = threadIdx.x;
    const float* x = X + (size_t)row * DQ;
    const float* r = R + (size_t)row * DQ;
    float y0 = x[t]       + r[t];
    float y1 = x[t + 256] + r[t + 256];
    float y2 = x[t + 512] + r[t + 512];
    float s = y0 + y1 + y2;
    float qv = y0 * y0 + y1 * y1 + y2 * y2;

    __shared__ float ss[8], qq[8];
#pragma unroll
    for (int o = 16; o > 0; o >>= 1) {
        s  += __shfl_xor_sync(0xffffffffu, s, o);
        qv += __shfl_xor_sync(0xffffffffu, qv, o);
    }
    if ((t & 31) == 0) { ss[t >> 5] = s; qq[t >> 5] = qv; }
    __syncthreads();
    if (t < 32) {
        float s2 = (t < 8) ? ss[t] : 0.f;
        float q2 = (t < 8) ? qq[t] : 0.f;
#pragma unroll
        for (int o = 4; o > 0; o >>= 1) {
            s2 += __shfl_xor_sync(0xffffffffu, s2, o);
            q2 += __shfl_xor_sync(0xffffffffu, q2, o);
        }
        if (t == 0) { ss[0] = s2; qq[0] = q2; }
    }
    __syncthreads();
    const float invD = 1.f / (float)DQ;
    float mean = ss[0] * invD;
    float var  = qq[0] * invD - mean * mean;
    float inv  = rsqrtf(var + 1e-5f);
    float* o = out + (size_t)row * DQ;
    o[t]       = (y0 - mean) * inv * g[t]       + b[t];
    o[t + 256] = (y1 - mean) * inv * g[t + 256] + b[t + 256];
    o[t + 512] = (y2 - mean) * inv * g[t + 512] + b[t + 512];
}

// =================================================================
// Kernel 5b: add_ln reading residual from permuted [h][i][sd] layout.
// =================================================================
__global__ __launch_bounds__(256) void add_ln_perm(
    const float* __restrict__ X, const float* __restrict__ Rp,
    const float* __restrict__ g, const float* __restrict__ b,
    float* __restrict__ out)
{
    const int row = blockIdx.x;          // s*256 + i
    const int s = row >> 8;
    const int i = row & 255;
    const int t = threadIdx.x;
    const float* x = X + (size_t)row * DQ;

    float y[3];
#pragma unroll
    for (int u = 0; u < 3; u++) {
        const int cc = t + u * 256;
        const int h = cc >> 6, d = cc & 63;
        y[u] = x[cc] + Rp[((size_t)(h * 256 + i)) * 8192 + s * 64 + d];
    }
    float sm = y[0] + y[1] + y[2];
    float qv = y[0] * y[0] + y[1] * y[1] + y[2] * y[2];

    __shared__ float ss[8], qq[8];
#pragma unroll
    for (int o = 16; o > 0; o >>= 1) {
        sm += __shfl_xor_sync(0xffffffffu, sm, o);
        qv += __shfl_xor_sync(0xffffffffu, qv, o);
    }
    if ((t & 31) == 0) { ss[t >> 5] = sm; qq[t >> 5] = qv; }
    __syncthreads();
    if (t < 32) {
        float s2 = (t < 8) ? ss[t] : 0.f;
        float q2 = (t < 8) ? qq[t] : 0.f;
#pragma unroll
        for (int o = 4; o > 0; o >>= 1) {
            s2 += __shfl_xor_sync(0xffffffffu, s2, o);
            q2 += __shfl_xor_sync(0xffffffffu, q2, o);
        }
        if (t == 0) { ss[0] = s2; qq[0] = q2; }
    }
    __syncthreads();
    const float invD = 1.f / (float)DQ;
    float mean = ss[0] * invD;
    float var  = qq[0] * invD - mean * mean;
    float inv  = rsqrtf(var + 1e-5f);
    float* o = out + (size_t)row * DQ;
#pragma unroll
    for (int u = 0; u < 3; u++) {
        const int cc = t + u * 256;
        o[cc] = (y[u] - mean) * inv * g[cc] + b[cc];
    }
}

// =================================================================
// Kernel 7: column attention — flash-style single pass (R12 winner)
// =================================================================
__global__ __launch_bounds__(128, 3) void col_attn_kernel(
    const float* __restrict__ qkv, float* __restrict__ out)
{
    __shared__ float Kt[128][68];
    __shared__ float Vt[128][68];

    const int l = blockIdx.x;
    const int h = blockIdx.y;
    const int t = threadIdx.x;
    const int base = l * N3Q + h * DHQ;

    const float* krow = qkv + (size_t)(t * LQ) * N3Q + base + DQ;
    const float* vrow = krow + DQ;
#pragma unroll
    for (int c = 0; c < DHQ; c += 4) {
        *(float4*)&Kt[t][c] = *(const float4*)(krow + c);
        *(float4*)&Vt[t][c] = *(const float4*)(vrow + c);
    }
    float q[DHQ];
    const float* qrow = qkv + (size_t)(t * LQ) * N3Q + base;
#pragma unroll
    for (int c = 0; c < DHQ; c += 4) {
        float4 qf = *(const float4*)(qrow + c);
        q[c] = qf.x; q[c + 1] = qf.y; q[c + 2] = qf.z; q[c + 3] = qf.w;
    }

    float o[DHQ];
#pragma unroll
    for (int d = 0; d < DHQ; d++) o[d] = 0.f;
    float m = -3.4e38f, ssum = 0.f;
    __syncthreads();

    for (int j = 0; j < SQ; j++) {
        float a0 = 0.f, a1 = 0.f, a2 = 0.f, a3 = 0.f;
#pragma unroll
        for (int c = 0; c < DHQ; c += 4) {
            float4 k4 = *(const float4*)&Kt[j][c];
            a0 += q[c]     * k4.x;
            a1 += q[c + 1] * k4.y;
            a2 += q[c + 2] * k4.z;
            a3 += q[c + 3] * k4.w;
        }
        float sgm = (a0 + a1) + (a2 + a3);

        if (sgm > m) {
            float corr = expf(m - sgm);
            ssum *= corr;
#pragma unroll
            for (int d = 0; d < DHQ; d++) o[d] *= corr;
            m = sgm;
        }
        float p = expf(sgm - m);
        ssum += p;
#pragma unroll
        for (int c = 0; c < DHQ; c += 4) {
            float4 v4 = *(const float4*)&Vt[j][c];
            o[c]     += p * v4.x;
            o[c + 1] += p * v4.y;
            o[c + 2] += p * v4.z;
            o[c + 3] += p * v4.w;
        }
    }

    const float inv = 1.f / ssum;
    float* orow = out + (size_t)(t * LQ + l) * DQ + h * DHQ;
#pragma unroll
    for (int d = 0; d < DHQ; d += 4) {
        float4 v = make_float4(o[d] * inv, o[d + 1] * inv, o[d + 2] * inv, o[d + 3] * inv);
        *(float4*)(orow + d) = v;
    }
}

// =================================================================
extern "C" void kernel_launch(void* const* d_in, const int* in_sizes, int n_in,
                              void* d_out, int out_size)
{
    const float* x     = (const float*)d_in[0];
    const float* w_row = (const float*)d_in[1];
    const float* b_row = (const float*)d_in[2];
    const float* w_col = (const float*)d_in[3];
    const float* b_col = (const float*)d_in[4];
    const float* g1    = (const float*)d_in[5];
    const float* beta1 = (const float*)d_in[6];
    const float* g2    = (const float*)d_in[7];
    const float* beta2 = (const float*)d_in[8];
    float* out = (float*)d_out;

    float *qkv, *attn, *tmp, *out1, *wsp;
    uint32_t* qksp;
    cudaGetSymbolAddress((void**)&qkv,  g_qkv);
    cudaGetSymbolAddress((void**)&attn, g_attn);
    cudaGetSymbolAddress((void**)&tmp,  g_tmp);
    cudaGetSymbolAddress((void**)&out1, g_out1);
    cudaGetSymbolAddress((void**)&wsp,  g_wsplit);
    cudaGetSymbolAddress((void**)&qksp, g_qksp);

    // int8 quant buffers: A in g_tmp, W in g_wsplit
    uint8_t* a8h = (uint8_t*)tmp;
    uint8_t* a8l = a8h + (size_t)MQ * DQ;
    float*   saA = (float*)(a8l + (size_t)MQ * DQ);      // 32768 floats
    uint8_t* w8h = (uint8_t*)wsp;
    uint8_t* w8l = w8h + (size_t)N3Q * DQ;
    float*   saW = (float*)(w8l + (size_t)N3Q * DQ);     // 2304 floats

    // attn bf16 splits (reuse wsp after W quant consumed)
    __nv_bfloat16* at_hi = (__nv_bfloat16*)wsp;
    __nv_bfloat16* at_lo = at_hi + (size_t)AT_ELE;

    cudaFuncSetAttribute(row_logits_mma,
                         cudaFuncAttributeMaxDynamicSharedMemorySize, MV2_SMEM);
    cudaFuncSetAttribute(row_av_mma,
                         cudaFuncAttributeMaxDynamicSharedMemorySize, MV2_SMEM);
    cudaFuncSetAttribute(split_v,
                         cudaFuncAttributeMaxDynamicSharedMemorySize, 64 * 258 * 4);

    dim3 i8_grid(N3Q / 64, MQ / 128);   // (36, 256)

    // --- row stage ---
    quant_rows<<<MQ, 192>>>(x, (uint32_t*)a8h, (uint32_t*)a8l, saA);
    quant_rows<<<N3Q, 192>>>(w_row, (uint32_t*)w8h, (uint32_t*)w8l, saW);
    qkv_gemm_i8<<<i8_grid, 256>>>(a8h, a8l, w8h, w8l, saA, saW, b_row, qkv);

    split_qk<<<2 * QK_U32 / 256, 256>>>(qkv, qksp);
    row_logits_mma<<<dim3(2, 2, HQ * NSP), 256, MV2_SMEM>>>(qksp, out1);
    softmax_row<<<HQ * LQ, 256>>>(out1, attn);

    split_bf16<<<(HQ * LQ * LQ / 4) / 256, 256>>>(attn, at_hi, at_lo, HQ * LQ * LQ / 4);
    split_v<<<dim3(SQ, HQ), 256, 64 * 258 * 4>>>(qkv, qksp);
    row_av_mma<<<dim3(64, 2, HQ), 256, MV2_SMEM>>>((uint32_t*)at_hi, qksp, tmp);
    add_ln_perm<<<MQ, 256>>>(x, tmp, g1, beta1, out1);

    // --- column stage ---
    quant_rows<<<MQ, 192>>>(out1, (uint32_t*)a8h, (uint32_t*)a8l, saA);
    quant_rows<<<N3Q, 192>>>(w_col, (uint32_t*)w8h, (uint32_t*)w8l, saW);
    qkv_gemm_i8<<<i8_grid, 256>>>(a8h, a8l, w8h, w8l, saA, saW, b_col, qkv);

    col_attn_kernel<<<dim3(LQ, HQ), 128>>>(qkv, tmp);
    add_ln<<<MQ, 256>>>(out1, tmp, g2, beta2, out);
}